// round 6
// baseline (speedup 1.0000x reference)
#include <cuda_runtime.h>
#include <cstdint>

#define BSZ 512
#define NN 1000
#define D 128
#define STR 384   // K_att/V_att innermost stride in floats (3 layers * 128)
#define NW 8      // warps per CTA
#define DEPTH 4   // ring depth (nodes in flight per warp)

__device__ __forceinline__ float4 zero4() { return make_float4(0.f, 0.f, 0.f, 0.f); }

__device__ __forceinline__ uint32_t smem_u32(const void* p) {
    uint32_t a;
    asm("{ .reg .u64 t; cvta.to.shared.u64 t, %1; cvt.u32.u64 %0, t; }" : "=r"(a) : "l"(p));
    return a;
}
__device__ __forceinline__ void mbar_init(uint32_t a, uint32_t c) {
    asm volatile("mbarrier.init.shared.b64 [%0], %1;" :: "r"(a), "r"(c) : "memory");
}
__device__ __forceinline__ void mbar_expect_tx(uint32_t a, uint32_t b) {
    asm volatile("mbarrier.arrive.expect_tx.shared.b64 _, [%0], %1;" :: "r"(a), "r"(b) : "memory");
}
__device__ __forceinline__ void mbar_wait(uint32_t a, uint32_t ph) {
    uint32_t done;
    do {
        asm volatile("{\n\t.reg .pred p;\n\t"
                     "mbarrier.try_wait.parity.acquire.cta.shared::cta.b64 p, [%1], %2, 0x989680;\n\t"
                     "selp.b32 %0, 1, 0, p;\n\t}"
                     : "=r"(done) : "r"(a), "r"(ph) : "memory");
    } while (!done);
}
__device__ __forceinline__ void bulk_g2s(uint32_t dst, const void* src, uint32_t bytes, uint32_t mbar) {
    asm volatile("cp.async.bulk.shared::cluster.global.mbarrier::complete_tx::bytes [%0], [%1], %2, [%3];"
                 :: "r"(dst), "l"(src), "r"(bytes), "r"(mbar) : "memory");
}

// One CTA per batch, 8 warps. Warp w owns compacted positions w, w+8, ...
// Lane 0 of each warp streams the node's 512B K/V slices into a 4-deep
// per-warp smem ring via cp.async.bulk (TMA engine, bypasses L1tex);
// the warp consumes via mbarrier parity. Phase counter persists across layers.

__global__ __launch_bounds__(256, 4)
void decoder_fused_kernel(
    const float* __restrict__ query,
    const float* __restrict__ K_att,
    const float* __restrict__ V_att,
    const int* __restrict__ mask,          // bool serialized as int32
    const float* __restrict__ W0_w,
    const float* __restrict__ W0_b,
    const float* __restrict__ Wq_w,
    const float* __restrict__ Wq_b,
    float* __restrict__ out)
{
    __shared__ int nlist[NN];
    __shared__ int cnt_s;
    __shared__ __align__(1024) float ring[NW * DEPTH * 256];  // [warp][slot][K 512B | V 512B] = 32 KB
    __shared__ __align__(8) unsigned long long bars[NW * DEPTH];
    __shared__ __align__(16) float qs[D];
    __shared__ __align__(16) float mo[D];
    __shared__ float m_s[NW][32];
    __shared__ float l_s[NW][32];
    __shared__ __align__(16) float4 a_s[NW][32];
    __shared__ float M2s, L2s;

    const int b = blockIdx.x;
    const int tid = threadIdx.x;
    const int wid = tid >> 5;
    const int lane = tid & 31;
    const int loff = 4 * lane;

    if (tid < D) qs[tid] = query[(size_t)b * D + tid];

    const uint32_t ring_base = smem_u32(ring) + (uint32_t)wid * DEPTH * 1024u;
    const uint32_t bar_base  = smem_u32(bars) + (uint32_t)wid * DEPTH * 8u;

    // per-warp mbarrier init (count=1: lane0's arrive.expect_tx)
    if (lane == 0) {
        #pragma unroll
        for (int s = 0; s < DEPTH; ++s) mbar_init(bar_base + 8u * s, 1);
    }
    __syncwarp();

    // ---- Compact unmasked node list (warp 0) ----
    const int* mrow = mask + (size_t)b * NN;
    if (wid == 0) {
        int base = 0;
        for (int start = 0; start < NN; start += 32) {
            int n = start + lane;
            bool keep = (n < NN) && (mrow[n] == 0);
            unsigned bal = __ballot_sync(0xffffffffu, keep);
            if (keep) {
                int pos = base + __popc(bal & ((1u << lane) - 1u));
                nlist[pos] = n;
            }
            base += __popc(bal);
        }
        if (lane == 0) cnt_s = base;
    }
    __syncthreads();
    const int cnt = cnt_s;

    const float* Kb = K_att + (size_t)b * NN * STR;
    const float* Vb = V_att + (size_t)b * NN * STR;

    unsigned git = 0;  // persistent per-warp pipeline counter (slot = git&3, parity = (git>>2)&1)

    // ==================== Layers 0 and 1: 8-head MHA + W0 linear ====================
    for (int l = 0; l < 2; ++l) {
        const int cbase = l * D;

        // prologue: fill up to DEPTH stages
        if (lane == 0) {
            #pragma unroll
            for (int s = 0; s < DEPTH; ++s) {
                int pos = wid + s * NW;
                if (pos < cnt) {
                    unsigned sl = (git + s) & (DEPTH - 1);
                    uint32_t mb = bar_base + 8u * sl;
                    uint32_t dst = ring_base + sl * 1024u;
                    const float* src = Kb + (size_t)nlist[pos] * STR + cbase;
                    mbar_expect_tx(mb, 1024);
                    bulk_g2s(dst, src, 512, mb);
                    bulk_g2s(dst + 512u, Vb + (size_t)nlist[pos] * STR + cbase, 512, mb);
                }
            }
        }
        __syncwarp();

        const float4 q4 = *(const float4*)(qs + loff);
        float m = -1e30f, lsum = 0.0f;
        float4 acc = zero4();

        for (int p = wid; p < cnt; p += NW, ++git) {
            const unsigned sl = git & (DEPTH - 1);
            const unsigned ph = (git >> 2) & 1u;
            mbar_wait(bar_base + 8u * sl, ph);
            const float* slot = (const float*)(ring + (size_t)wid * DEPTH * 256 + sl * 256);
            const float4 k4 = *(const float4*)(slot + lane * 4);
            const float4 v4 = *(const float4*)(slot + 128 + lane * 4);
            __syncwarp();
            const int pi = p + NW * DEPTH;
            if (lane == 0 && pi < cnt) {
                uint32_t mb = bar_base + 8u * sl;
                uint32_t dst = ring_base + sl * 1024u;
                size_t o = (size_t)nlist[pi] * STR + cbase;
                mbar_expect_tx(mb, 1024);
                bulk_g2s(dst, Kb + o, 512, mb);
                bulk_g2s(dst + 512u, Vb + o, 512, mb);
            }

            float s = k4.x * q4.x + k4.y * q4.y + k4.z * q4.z + k4.w * q4.w;
            s += __shfl_xor_sync(0xffffffffu, s, 1);
            s += __shfl_xor_sync(0xffffffffu, s, 2);
            s *= 0.25f;  // 1/sqrt(16)

            const float mn = fmaxf(m, s);
            const float c = __expf(m - mn);
            const float e = __expf(s - mn);
            lsum = lsum * c + e;
            acc.x = acc.x * c + e * v4.x;
            acc.y = acc.y * c + e * v4.y;
            acc.z = acc.z * c + e * v4.z;
            acc.w = acc.w * c + e * v4.w;
            m = mn;
        }

        m_s[wid][lane] = m;
        l_s[wid][lane] = lsum;
        a_s[wid][lane] = acc;
        __syncthreads();

        if (tid < 32) {
            float M = m_s[0][lane];
            #pragma unroll
            for (int w = 1; w < NW; ++w) M = fmaxf(M, m_s[w][lane]);
            float L = 0.f;
            float ax = 0.f, ay = 0.f, az = 0.f, aw = 0.f;
            #pragma unroll
            for (int w = 0; w < NW; ++w) {
                const float c = __expf(m_s[w][lane] - M);
                L += l_s[w][lane] * c;
                const float4 a = a_s[w][lane];
                ax += a.x * c; ay += a.y * c; az += a.z * c; aw += a.w * c;
            }
            const float inv = 1.0f / L;
            mo[4 * lane + 0] = ax * inv;
            mo[4 * lane + 1] = ay * inv;
            mo[4 * lane + 2] = az * inv;
            mo[4 * lane + 3] = aw * inv;
        }
        __syncthreads();

        if (tid < D) {
            const float* Wr = W0_w + tid * D;
            float a2 = W0_b[tid];
            #pragma unroll 8
            for (int d = 0; d < D; ++d) a2 = fmaf(mo[d], Wr[d], a2);
            qs[tid] = a2;
        }
        __syncthreads();
    }

    // ==================== Layer 2: q_final = q @ Wq.T + b; 1-head, clip=10 ====================
    if (tid < D) {
        const float* Wr = Wq_w + tid * D;
        float a2 = Wq_b[tid];
        #pragma unroll 8
        for (int d = 0; d < D; ++d) a2 = fmaf(qs[d], Wr[d], a2);
        mo[tid] = a2;
    }
    __syncthreads();

    {
        const int cbase = 2 * D;
        const float4 q4 = *(const float4*)(mo + loff);
        float* orow = out + (size_t)b * NN;

        if (lane == 0) {
            #pragma unroll
            for (int s = 0; s < DEPTH; ++s) {
                int pos = wid + s * NW;
                if (pos < cnt) {
                    unsigned sl = (git + s) & (DEPTH - 1);
                    uint32_t mb = bar_base + 8u * sl;
                    mbar_expect_tx(mb, 512);
                    bulk_g2s(ring_base + sl * 1024u, Kb + (size_t)nlist[pos] * STR + cbase, 512, mb);
                }
            }
        }
        __syncwarp();

        float m = -1e30f, lsum = 0.0f;
        for (int p = wid; p < cnt; p += NW, ++git) {
            const unsigned sl = git & (DEPTH - 1);
            const unsigned ph = (git >> 2) & 1u;
            mbar_wait(bar_base + 8u * sl, ph);
            const float* slot = (const float*)(ring + (size_t)wid * DEPTH * 256 + sl * 256);
            const float4 k4 = *(const float4*)(slot + lane * 4);
            __syncwarp();
            const int pi = p + NW * DEPTH;
            if (lane == 0 && pi < cnt) {
                uint32_t mb = bar_base + 8u * sl;
                mbar_expect_tx(mb, 512);
                bulk_g2s(ring_base + sl * 1024u, Kb + (size_t)nlist[pi] * STR + cbase, 512, mb);
            }

            float s = k4.x * q4.x + k4.y * q4.y + k4.z * q4.z + k4.w * q4.w;
            #pragma unroll
            for (int d = 1; d < 32; d <<= 1)
                s += __shfl_xor_sync(0xffffffffu, s, d);
            s *= 0.08838834764831845f;           // 1/sqrt(128)
            s = 10.0f * (1.0f - __fdividef(2.0f, __expf(2.0f * s) + 1.0f));  // 10*tanh

            if (lane == 0) orow[nlist[p]] = s;
            const float mn = fmaxf(m, s);
            lsum = lsum * __expf(m - mn) + __expf(s - mn);
            m = mn;
        }

        if (lane == 0) { m_s[wid][0] = m; l_s[wid][0] = lsum; }
        __syncthreads();
        if (tid == 0) {
            float M = m_s[0][0];
            #pragma unroll
            for (int w = 1; w < NW; ++w) M = fmaxf(M, m_s[w][0]);
            float L = 0.f;
            #pragma unroll
            for (int w = 0; w < NW; ++w) L += l_s[w][0] * __expf(m_s[w][0] - M);
            M2s = M;
            L2s = 1.0f / L;
        }
        __syncthreads();

        const float M = M2s, Li = L2s;
        for (int n = tid; n < NN; n += 256) {
            float v = 0.0f;
            if (mrow[n] == 0) v = __expf(orow[n] - M) * Li;
            orow[n] = v;
        }
    }
}

extern "C" void kernel_launch(void* const* d_in, const int* in_sizes, int n_in,
                              void* d_out, int out_size) {
    const float* query = (const float*)d_in[0];
    const float* K_att = (const float*)d_in[1];
    const float* V_att = (const float*)d_in[2];
    const int*   mask  = (const int*)d_in[3];
    const float* W0_w  = (const float*)d_in[4];
    const float* W0_b  = (const float*)d_in[5];
    const float* Wq_w  = (const float*)d_in[6];
    const float* Wq_b  = (const float*)d_in[7];
    float* out = (float*)d_out;

    decoder_fused_kernel<<<BSZ, 256>>>(query, K_att, V_att, mask,
                                       W0_w, W0_b, Wq_w, Wq_b, out);
}